// round 3
// baseline (speedup 1.0000x reference)
#include <cuda_runtime.h>

#define MM   128   // padded image side
#define NP   64    // patch side
#define NC   4     // channels / positions
#define C0   32    // (M - N) / 2
#define RB   16    // rows per thread (contiguous band)

// block (64, 4, 2): tx = output column, ty = row band (16 rows),
// tz = channel pair (channels 2*tz, 2*tz+1). 512 threads, 3 CTAs/SM.
__global__ __launch_bounds__(512, 3)
void extract_patches_kernel(const float* __restrict__ img,
                            const float* __restrict__ pos,
                            float* __restrict__ out)
{
    const int b = blockIdx.x;
    const float* I = img + (size_t)b * (MM * MM);

    // Stage the 8 position scalars: layout (B,1,2,C); dim0 = ox, dim1 = oy.
    __shared__ float spos[2 * NC];
    if (threadIdx.y == 0 && threadIdx.z == 0 && threadIdx.x < 2 * NC)
        spos[threadIdx.x] = pos[(size_t)b * (2 * NC) + threadIdx.x];
    __syncthreads();

    const int tx = threadIdx.x;           // output column j in [0, 64)
    const int i0 = threadIdx.y * RB;      // first row of this thread's band
    const int cb = threadIdx.z * 2;       // first of this thread's 2 channels

    // Per-channel setup (2 channels): horizontal weight/index, initial
    // vertical index, and the horizontally-lerped TOP row (hprev).
    float wx[2], hprev[2], yif[2], oyv[2];
    int   off[2];
#pragma unroll
    for (int u = 0; u < 2; u++) {
        float ox = spos[cb + u];
        oyv[u]   = spos[NC + cb + u];

        float xx = (float)(tx + C0) + ox;
        float x0 = floorf(xx);
        wx[u]    = xx - x0;
        int xi   = (int)x0;

        float yy = (float)(i0 + C0) + oyv[u];
        float y0 = floorf(yy);
        yif[u]   = y0;
        int yi   = (int)y0;

        // SHIFT_MAX=20, c0=32: yi,xi in [12,51]; deepest access yi+RB rows,
        // xi+1 cols stays < 128 -> the reference valid-mask is always true.
        off[u] = yi * MM + xi;
        float a0 = __ldg(I + off[u]);
        float a1 = __ldg(I + off[u] + 1);
        hprev[u] = fmaf(a1 - a0, wx[u], a0);   // H(top row)
    }

    // Output: (B, 64, 64, 4) floats; this thread writes channels cb..cb+1
    // at column tx for rows i0..i0+15. 8-byte aligned float2 stores.
    float* ob = out + ((size_t)b * (NP * NP) + (size_t)i0 * NP + tx) * NC + cb;

    // Walk RB contiguous rows; each step loads only the new BOTTOM row taps
    // (2 per channel) and reuses hprev as the top H-row.
#pragma unroll
    for (int k = 0; k < RB; k++) {
        float2 res;
#pragma unroll
        for (int u = 0; u < 2; u++) {
            off[u] += MM;
            float b0 = __ldg(I + off[u]);
            float b1 = __ldg(I + off[u] + 1);
            float hnew = fmaf(b1 - b0, wx[u], b0);      // H(bottom row)

            float yy = (float)(i0 + k + C0) + oyv[u];
            float wy = yy - (yif[u] + (float)k);

            float r  = fmaf(hnew - hprev[u], wy, hprev[u]);
            hprev[u] = hnew;
            if (u == 0) res.x = r; else res.y = r;
        }
        // Streaming store: output is never re-read; keep L2 for image lines.
        __stcs(reinterpret_cast<float2*>(ob + (size_t)k * (NP * NC)), res);
    }
}

extern "C" void kernel_launch(void* const* d_in, const int* in_sizes, int n_in,
                              void* d_out, int out_size)
{
    const float* img = (const float*)d_in[0];   // padded_obj (B,128,128,1)
    const float* pos = (const float*)d_in[1];   // positions  (B,1,2,4)
    float* out = (float*)d_out;                 // (B,64,64,4)

    int B = in_sizes[0] / (MM * MM);
    dim3 block(64, 4, 2);
    extract_patches_kernel<<<B, block>>>(img, pos, out);
}

// round 4
// speedup vs baseline: 1.0610x; 1.0610x over previous
#include <cuda_runtime.h>

#define MM   128   // padded image side
#define NP   64    // patch side
#define NC   4     // channels / positions
#define C0   32    // (M - N) / 2
#define RB   16    // rows per thread (contiguous band)

// block (2, 64, 4): tx = channel PAIR (fastest -> warp covers 16 cols x 2 pairs,
// making float2 stores a single contiguous 256B run per warp, full sectors),
// ty = output column, tz = row band (16 rows). 512 threads, 3 CTAs/SM.
__global__ __launch_bounds__(512, 3)
void extract_patches_kernel(const float* __restrict__ img,
                            const float* __restrict__ pos,
                            float* __restrict__ out)
{
    const int b = blockIdx.x;
    const float* I = img + (size_t)b * (MM * MM);

    // Stage the 8 position scalars: layout (B,1,2,C); dim0 = ox, dim1 = oy.
    __shared__ float spos[2 * NC];
    const int lid = threadIdx.x + 2 * threadIdx.y + 128 * threadIdx.z;
    if (lid < 2 * NC)
        spos[lid] = pos[(size_t)b * (2 * NC) + lid];
    __syncthreads();

    const int col = threadIdx.y;          // output column j in [0, 64)
    const int i0  = threadIdx.z * RB;     // first row of this thread's band
    const int cb  = threadIdx.x * 2;      // first of this thread's 2 channels

    // Per-channel setup (2 channels): horizontal weight/index, initial
    // vertical index, and the horizontally-lerped TOP row (hprev).
    float wx[2], hprev[2], yif[2], oyv[2];
    int   off[2];
#pragma unroll
    for (int u = 0; u < 2; u++) {
        float ox = spos[cb + u];
        oyv[u]   = spos[NC + cb + u];

        float xx = (float)(col + C0) + ox;
        float x0 = floorf(xx);
        wx[u]    = xx - x0;
        int xi   = (int)x0;

        float yy = (float)(i0 + C0) + oyv[u];
        float y0 = floorf(yy);
        yif[u]   = y0;
        int yi   = (int)y0;

        // SHIFT_MAX=20, c0=32: yi,xi in [12,51]; deepest access yi+RB rows,
        // xi+1 cols stays < 128 -> the reference valid-mask is always true.
        off[u] = yi * MM + xi;
        float a0 = __ldg(I + off[u]);
        float a1 = __ldg(I + off[u] + 1);
        hprev[u] = fmaf(a1 - a0, wx[u], a0);   // H(top row)
    }

    // Output: (B, 64, 64, 4) floats; this thread writes channels cb..cb+1
    // at column `col` for rows i0..i0+15. 8-byte aligned float2 stores that
    // are warp-contiguous (256B / full 32B sectors per warp).
    float* ob = out + ((size_t)b * (NP * NP) + (size_t)i0 * NP + col) * NC + cb;

    // Walk RB contiguous rows; each step loads only the new BOTTOM row taps
    // (2 per channel) and reuses hprev as the top H-row.
#pragma unroll
    for (int k = 0; k < RB; k++) {
        float2 res;
#pragma unroll
        for (int u = 0; u < 2; u++) {
            off[u] += MM;
            float b0 = __ldg(I + off[u]);
            float b1 = __ldg(I + off[u] + 1);
            float hnew = fmaf(b1 - b0, wx[u], b0);      // H(bottom row)

            // wy per-row, matching the reference's yy = (i+c0)+oy arithmetic.
            float yy = (float)(i0 + k + C0) + oyv[u];
            float wy = yy - (yif[u] + (float)k);

            float r  = fmaf(hnew - hprev[u], wy, hprev[u]);
            hprev[u] = hnew;
            if (u == 0) res.x = r; else res.y = r;
        }
        // Streaming store: output is never re-read; full-sector coverage now,
        // so no read-modify-write amplification and no L2 pollution.
        __stcs(reinterpret_cast<float2*>(ob + (size_t)k * (NP * NC)), res);
    }
}

extern "C" void kernel_launch(void* const* d_in, const int* in_sizes, int n_in,
                              void* d_out, int out_size)
{
    const float* img = (const float*)d_in[0];   // padded_obj (B,128,128,1)
    const float* pos = (const float*)d_in[1];   // positions  (B,1,2,4)
    float* out = (float*)d_out;                 // (B,64,64,4)

    int B = in_sizes[0] / (MM * MM);
    dim3 block(2, 64, 4);
    extract_patches_kernel<<<B, block>>>(img, pos, out);
}